// round 1
// baseline (speedup 1.0000x reference)
#include <cuda_runtime.h>
#include <cuda_bf16.h>
#include <math.h>

#define T_TOT   16384
#define H_DIM   1024
#define I_DIM   512
#define E_NUM   8
#define TOPK    2
#define NASSIGN (T_TOT * TOPK)

// ---------------- scratch (static device globals; no allocation) ----------------
__device__ int   g_topk_idx[NASSIGN];
__device__ float g_topk_w[NASSIGN];
__device__ int   g_cnt[E_NUM];
__device__ int   g_off[E_NUM];
__device__ int   g_fill[E_NUM];
__device__ int   g_tok[NASSIGN];                 // token id per assignment row
__device__ float g_aw[NASSIGN];                  // combine weight per assignment row
__device__ float g_inter[(size_t)NASSIGN * I_DIM];   // 64 MB
__device__ float g_sinter[(size_t)T_TOT * I_DIM];    // 32 MB

__device__ __forceinline__ float gelu_exact(float x) {
    return 0.5f * x * (1.0f + erff(x * 0.70710678118654752f));
}

// ---------------- init ----------------
__global__ void init_kernel() {
    if (threadIdx.x < E_NUM) g_cnt[threadIdx.x] = 0;
}

// ---------------- router: fp32 logits, top-2, renormalized weights ----------------
__global__ void __launch_bounds__(256) router_kernel(const float* __restrict__ X,
                                                     const float* __restrict__ GW) {
    __shared__ float sgw[E_NUM * H_DIM];   // 32 KB
    for (int i = threadIdx.x; i < E_NUM * H_DIM; i += 256) sgw[i] = GW[i];
    __syncthreads();

    const int warp = threadIdx.x >> 5;
    const int lane = threadIdx.x & 31;
    const int t = blockIdx.x * 8 + warp;
    if (t >= T_TOT) return;

    const float* x = X + (size_t)t * H_DIM;
    float acc[E_NUM];
#pragma unroll
    for (int e = 0; e < E_NUM; e++) acc[e] = 0.0f;

    for (int h = lane; h < H_DIM; h += 32) {
        const float xv = x[h];
#pragma unroll
        for (int e = 0; e < E_NUM; e++) acc[e] = fmaf(xv, sgw[e * H_DIM + h], acc[e]);
    }
#pragma unroll
    for (int e = 0; e < E_NUM; e++) {
#pragma unroll
        for (int o = 16; o > 0; o >>= 1) acc[e] += __shfl_down_sync(0xffffffffu, acc[e], o);
    }

    if (lane == 0) {
        float l0 = -1e30f, l1 = -1e30f;
        int   i0 = 0,      i1 = 0;
#pragma unroll
        for (int e = 0; e < E_NUM; e++) {
            const float v = acc[e];
            if (v > l0)      { l1 = l0; i1 = i0; l0 = v; i0 = e; }
            else if (v > l1) { l1 = v; i1 = e; }
        }
        // softmax denominator cancels in top-k renormalization
        const float w1 = expf(l1 - l0);
        const float inv = 1.0f / (1.0f + w1);
        g_topk_idx[t * 2 + 0] = i0;
        g_topk_idx[t * 2 + 1] = i1;
        g_topk_w[t * 2 + 0] = inv;
        g_topk_w[t * 2 + 1] = w1 * inv;
        atomicAdd(&g_cnt[i0], 1);
        atomicAdd(&g_cnt[i1], 1);
    }
}

// ---------------- scan (8 entries) ----------------
__global__ void scan_kernel() {
    if (threadIdx.x == 0 && blockIdx.x == 0) {
        int s = 0;
        for (int e = 0; e < E_NUM; e++) {
            g_off[e]  = s;
            g_fill[e] = s;
            s += g_cnt[e];
        }
    }
}

// ---------------- scatter tokens into per-expert segments ----------------
__global__ void __launch_bounds__(256) scatter_kernel() {
    const int t = blockIdx.x * 256 + threadIdx.x;
    if (t >= T_TOT) return;
#pragma unroll
    for (int k = 0; k < TOPK; k++) {
        const int   e = g_topk_idx[t * 2 + k];
        const float w = g_topk_w[t * 2 + k];
        const int   p = atomicAdd(&g_fill[e], 1);
        g_tok[p] = t;
        g_aw[p]  = w;
    }
}

// ---------------- fused gate+up GEMM with exact-GELU epilogue ----------------
// C tile 64x64, K tile 16, 256 threads, 4x4 microtile, two B operands share A.
template <bool ROUTED>
__global__ void __launch_bounds__(256) gateup_kernel(const float* __restrict__ X,
                                                     const float* __restrict__ Wg_all,
                                                     const float* __restrict__ Wu_all,
                                                     float* __restrict__ inter_out) {
    __shared__ float As[16][64];
    __shared__ float Bg[16][64];
    __shared__ float Bu[16][64];

    const int e    = ROUTED ? blockIdx.z : 0;
    const int cnt  = ROUTED ? g_cnt[e] : T_TOT;
    const int off  = ROUTED ? g_off[e] : 0;
    const int mb   = blockIdx.y * 64;
    if (mb >= cnt) return;
    const int nb   = blockIdx.x * 64;

    const float* Wg = Wg_all + (ROUTED ? (size_t)e * H_DIM * I_DIM : 0);
    const float* Wu = Wu_all + (ROUTED ? (size_t)e * H_DIM * I_DIM : 0);

    const int tid = threadIdx.x;

    // A loader: thread -> (row am, 4 consecutive k at ak); 4 threads cover 64B/row
    const int am = tid >> 2;
    const int ak = (tid & 3) * 4;
    int lrow = mb + am;
    if (lrow >= cnt) lrow = cnt - 1;
    const int arow = ROUTED ? g_tok[off + lrow] : lrow;
    const float* aptr = X + (size_t)arow * H_DIM + ak;

    // B loader: thread -> (k row bk, 4 consecutive n at bn)
    const int bn = (tid & 15) * 4;
    const int bk = tid >> 4;
    const float* bgp = Wg + (size_t)bk * I_DIM + nb + bn;
    const float* bup = Wu + (size_t)bk * I_DIM + nb + bn;

    const int ty = tid >> 4, tx = tid & 15;
    const int m0 = ty * 4,   n0 = tx * 4;

    float accg[4][4], accu[4][4];
#pragma unroll
    for (int i = 0; i < 4; i++)
#pragma unroll
        for (int j = 0; j < 4; j++) { accg[i][j] = 0.0f; accu[i][j] = 0.0f; }

    for (int k0 = 0; k0 < H_DIM; k0 += 16) {
        const float4 av  = *(const float4*)(aptr + k0);
        const float4 bgv = *(const float4*)(bgp + (size_t)k0 * I_DIM);
        const float4 buv = *(const float4*)(bup + (size_t)k0 * I_DIM);
        As[ak + 0][am] = av.x; As[ak + 1][am] = av.y;
        As[ak + 2][am] = av.z; As[ak + 3][am] = av.w;
        *(float4*)&Bg[bk][bn] = bgv;
        *(float4*)&Bu[bk][bn] = buv;
        __syncthreads();
#pragma unroll
        for (int k = 0; k < 16; k++) {
            const float4 a  = *(const float4*)(&As[k][m0]);
            const float4 b0 = *(const float4*)(&Bg[k][n0]);
            const float4 b1 = *(const float4*)(&Bu[k][n0]);
            const float aa[4]  = {a.x, a.y, a.z, a.w};
            const float bg4[4] = {b0.x, b0.y, b0.z, b0.w};
            const float bu4[4] = {b1.x, b1.y, b1.z, b1.w};
#pragma unroll
            for (int i = 0; i < 4; i++)
#pragma unroll
                for (int j = 0; j < 4; j++) {
                    accg[i][j] = fmaf(aa[i], bg4[j], accg[i][j]);
                    accu[i][j] = fmaf(aa[i], bu4[j], accu[i][j]);
                }
        }
        __syncthreads();
    }

#pragma unroll
    for (int i = 0; i < 4; i++) {
        const int lm = mb + m0 + i;
        if (lm >= cnt) continue;
        const size_t orow = (size_t)(ROUTED ? (off + lm) : lm) * I_DIM;
#pragma unroll
        for (int j = 0; j < 4; j++) {
            inter_out[orow + nb + n0 + j] = gelu_exact(accg[i][j]) * accu[i][j];
        }
    }
}

// ---------------- down-proj GEMM ----------------
// routed: out[tok] += w * inter @ Wd_e (atomic); shared: out[t] = sinter @ sWd (store)
template <bool ROUTED>
__global__ void __launch_bounds__(256) down_kernel(const float* __restrict__ Inter,
                                                   const float* __restrict__ Wd_all,
                                                   float* __restrict__ out) {
    __shared__ float As[16][64];
    __shared__ float Bs[16][64];

    const int e   = ROUTED ? blockIdx.z : 0;
    const int cnt = ROUTED ? g_cnt[e] : T_TOT;
    const int off = ROUTED ? g_off[e] : 0;
    const int mb  = blockIdx.y * 64;
    if (mb >= cnt) return;
    const int nb  = blockIdx.x * 64;

    const float* Wd = Wd_all + (ROUTED ? (size_t)e * I_DIM * H_DIM : 0);

    const int tid = threadIdx.x;
    const int am = tid >> 2;
    const int ak = (tid & 3) * 4;
    int lrow = mb + am;
    if (lrow >= cnt) lrow = cnt - 1;
    const float* aptr = Inter + (size_t)(off + lrow) * I_DIM + ak;

    const int bn = (tid & 15) * 4;
    const int bk = tid >> 4;
    const float* bp = Wd + (size_t)bk * H_DIM + nb + bn;

    const int ty = tid >> 4, tx = tid & 15;
    const int m0 = ty * 4,   n0 = tx * 4;

    float acc[4][4];
#pragma unroll
    for (int i = 0; i < 4; i++)
#pragma unroll
        for (int j = 0; j < 4; j++) acc[i][j] = 0.0f;

    for (int k0 = 0; k0 < I_DIM; k0 += 16) {
        const float4 av = *(const float4*)(aptr + k0);
        const float4 bv = *(const float4*)(bp + (size_t)k0 * H_DIM);
        As[ak + 0][am] = av.x; As[ak + 1][am] = av.y;
        As[ak + 2][am] = av.z; As[ak + 3][am] = av.w;
        *(float4*)&Bs[bk][bn] = bv;
        __syncthreads();
#pragma unroll
        for (int k = 0; k < 16; k++) {
            const float4 a = *(const float4*)(&As[k][m0]);
            const float4 b = *(const float4*)(&Bs[k][n0]);
            const float aa[4] = {a.x, a.y, a.z, a.w};
            const float bb[4] = {b.x, b.y, b.z, b.w};
#pragma unroll
            for (int i = 0; i < 4; i++)
#pragma unroll
                for (int j = 0; j < 4; j++)
                    acc[i][j] = fmaf(aa[i], bb[j], acc[i][j]);
        }
        __syncthreads();
    }

#pragma unroll
    for (int i = 0; i < 4; i++) {
        const int lm = mb + m0 + i;
        if (lm >= cnt) continue;
        if (ROUTED) {
            const int   tok = g_tok[off + lm];
            const float w   = g_aw[off + lm];
            float* op = out + (size_t)tok * H_DIM + nb + n0;
#pragma unroll
            for (int j = 0; j < 4; j++) atomicAdd(op + j, w * acc[i][j]);
        } else {
            float* op = out + (size_t)lm * H_DIM + nb + n0;
#pragma unroll
            for (int j = 0; j < 4; j++) op[j] = acc[i][j];
        }
    }
}

// ---------------- launch ----------------
extern "C" void kernel_launch(void* const* d_in, const int* in_sizes, int n_in,
                              void* d_out, int out_size) {
    const float* X   = (const float*)d_in[0];  // [T,H]
    const float* GW  = (const float*)d_in[1];  // [E,H]
    const float* Wg  = (const float*)d_in[2];  // [E,H,I]
    const float* Wu  = (const float*)d_in[3];  // [E,H,I]
    const float* Wd  = (const float*)d_in[4];  // [E,I,H]
    const float* sWg = (const float*)d_in[5];  // [H,SI]
    const float* sWu = (const float*)d_in[6];  // [H,SI]
    const float* sWd = (const float*)d_in[7];  // [SI,H]
    float* out = (float*)d_out;

    float* inter;   cudaGetSymbolAddress((void**)&inter,  g_inter);
    float* sinter;  cudaGetSymbolAddress((void**)&sinter, g_sinter);

    // routing pipeline
    init_kernel<<<1, 32>>>();
    router_kernel<<<T_TOT / 8, 256>>>(X, GW);
    scan_kernel<<<1, 32>>>();
    scatter_kernel<<<T_TOT / 256, 256>>>();

    // shared expert (writes every element of out -> clears the poison)
    gateup_kernel<false><<<dim3(I_DIM / 64, T_TOT / 64, 1), 256>>>(X, sWg, sWu, sinter);
    down_kernel<false><<<dim3(H_DIM / 64, T_TOT / 64, 1), 256>>>(sinter, sWd, out);

    // routed experts (scatter-add on top of shared-expert output)
    gateup_kernel<true><<<dim3(I_DIM / 64, T_TOT / 64, E_NUM), 256>>>(X, Wg, Wu, inter);
    down_kernel<true><<<dim3(H_DIM / 64, T_TOT / 64, E_NUM), 256>>>(inter, Wd, out);
}

// round 3
// speedup vs baseline: 2.6070x; 2.6070x over previous
#include <cuda_runtime.h>
#include <cuda_bf16.h>
#include <math.h>
#include <stdint.h>

#define T_TOT   16384
#define H_DIM   1024
#define I_DIM   512
#define E_NUM   8
#define TOPK    2
#define NASSIGN (T_TOT * TOPK)
#define KC      64

typedef __nv_bfloat16 bf16;

// ======================= scratch =======================
__device__ int   g_topk_idx[NASSIGN];
__device__ float g_topk_w[NASSIGN];
__device__ int   g_cnt[E_NUM];
__device__ int   g_off[E_NUM];
__device__ int   g_fill[E_NUM];
__device__ int   g_tok[NASSIGN];
__device__ float g_aw[NASSIGN];
__device__ int   g_pos[NASSIGN];     // (token,k) -> assignment row

__device__ __align__(16) bf16 g_xhi[(size_t)T_TOT * H_DIM];
__device__ __align__(16) bf16 g_xlo[(size_t)T_TOT * H_DIM];
__device__ __align__(16) bf16 g_wgT_hi[(size_t)E_NUM * I_DIM * H_DIM];
__device__ __align__(16) bf16 g_wgT_lo[(size_t)E_NUM * I_DIM * H_DIM];
__device__ __align__(16) bf16 g_wuT_hi[(size_t)E_NUM * I_DIM * H_DIM];
__device__ __align__(16) bf16 g_wuT_lo[(size_t)E_NUM * I_DIM * H_DIM];
__device__ __align__(16) bf16 g_wdT_hi[(size_t)E_NUM * H_DIM * I_DIM];
__device__ __align__(16) bf16 g_wdT_lo[(size_t)E_NUM * H_DIM * I_DIM];
__device__ __align__(16) bf16 g_swgT_hi[(size_t)I_DIM * H_DIM];
__device__ __align__(16) bf16 g_swgT_lo[(size_t)I_DIM * H_DIM];
__device__ __align__(16) bf16 g_swuT_hi[(size_t)I_DIM * H_DIM];
__device__ __align__(16) bf16 g_swuT_lo[(size_t)I_DIM * H_DIM];
__device__ __align__(16) bf16 g_swdT_hi[(size_t)H_DIM * I_DIM];
__device__ __align__(16) bf16 g_swdT_lo[(size_t)H_DIM * I_DIM];
__device__ __align__(16) bf16 g_ihi[(size_t)NASSIGN * I_DIM];
__device__ __align__(16) bf16 g_ilo[(size_t)NASSIGN * I_DIM];
__device__ __align__(16) bf16 g_sihi[(size_t)T_TOT * I_DIM];
__device__ __align__(16) bf16 g_silo[(size_t)T_TOT * I_DIM];
__device__ __align__(16) float g_dtmp[(size_t)NASSIGN * H_DIM];   // 128 MB

// ======================= helpers =======================
__device__ __forceinline__ uint32_t smem_u32(const void* p) {
    uint32_t a;
    asm("{ .reg .u64 t; cvta.to.shared.u64 t, %1; cvt.u32.u64 %0, t; }" : "=r"(a) : "l"(p));
    return a;
}
__device__ __forceinline__ void cp16(uint32_t dst, const void* src) {
    asm volatile("cp.async.cg.shared.global [%0], [%1], 16;" :: "r"(dst), "l"(src));
}
__device__ __forceinline__ void cp_commit() { asm volatile("cp.async.commit_group;" ::: "memory"); }
template <int N>
__device__ __forceinline__ void cp_wait() { asm volatile("cp.async.wait_group %0;" :: "n"(N) : "memory"); }

__device__ __forceinline__ void ldsm4(uint32_t* r, uint32_t addr) {
    asm volatile("ldmatrix.sync.aligned.m8n8.x4.shared.b16 {%0,%1,%2,%3}, [%4];"
                 : "=r"(r[0]), "=r"(r[1]), "=r"(r[2]), "=r"(r[3]) : "r"(addr));
}
__device__ __forceinline__ void mma16816(float* d, const uint32_t* a, uint32_t b0, uint32_t b1) {
    asm volatile("mma.sync.aligned.m16n8k16.row.col.f32.bf16.bf16.f32 "
                 "{%0,%1,%2,%3}, {%4,%5,%6,%7}, {%8,%9}, {%0,%1,%2,%3};"
                 : "+f"(d[0]), "+f"(d[1]), "+f"(d[2]), "+f"(d[3])
                 : "r"(a[0]), "r"(a[1]), "r"(a[2]), "r"(a[3]), "r"(b0), "r"(b1));
}
__device__ __forceinline__ float gelu_exact(float x) {
    return 0.5f * x * (1.0f + erff(x * 0.70710678118654752f));
}
__device__ __forceinline__ void splitpair(float v0, float v1, uint32_t& h, uint32_t& l) {
    __nv_bfloat162 ph = __floats2bfloat162_rn(v0, v1);
    float r0 = v0 - __low2float(ph);
    float r1 = v1 - __high2float(ph);
    __nv_bfloat162 pl = __floats2bfloat162_rn(r0, r1);
    h = *reinterpret_cast<uint32_t*>(&ph);
    l = *reinterpret_cast<uint32_t*>(&pl);
}

// ======================= routing =======================
__global__ void init_kernel() {
    if (threadIdx.x < E_NUM) g_cnt[threadIdx.x] = 0;
}

__global__ void __launch_bounds__(256) router_kernel(const float* __restrict__ X,
                                                     const float* __restrict__ GW) {
    __shared__ float sgw[E_NUM * H_DIM];
    for (int i = threadIdx.x; i < E_NUM * H_DIM; i += 256) sgw[i] = GW[i];
    __syncthreads();
    const int warp = threadIdx.x >> 5, lane = threadIdx.x & 31;
    const int t = blockIdx.x * 8 + warp;
    if (t >= T_TOT) return;
    const float* x = X + (size_t)t * H_DIM;
    float acc[E_NUM];
#pragma unroll
    for (int e = 0; e < E_NUM; e++) acc[e] = 0.0f;
    for (int h = lane; h < H_DIM; h += 32) {
        const float xv = x[h];
#pragma unroll
        for (int e = 0; e < E_NUM; e++) acc[e] = fmaf(xv, sgw[e * H_DIM + h], acc[e]);
    }
#pragma unroll
    for (int e = 0; e < E_NUM; e++)
#pragma unroll
        for (int o = 16; o > 0; o >>= 1) acc[e] += __shfl_down_sync(0xffffffffu, acc[e], o);
    if (lane == 0) {
        float l0 = -1e30f, l1 = -1e30f;
        int i0 = 0, i1 = 0;
#pragma unroll
        for (int e = 0; e < E_NUM; e++) {
            const float v = acc[e];
            if (v > l0)      { l1 = l0; i1 = i0; l0 = v; i0 = e; }
            else if (v > l1) { l1 = v; i1 = e; }
        }
        const float w1 = expf(l1 - l0);
        const float inv = 1.0f / (1.0f + w1);
        g_topk_idx[t * 2 + 0] = i0;
        g_topk_idx[t * 2 + 1] = i1;
        g_topk_w[t * 2 + 0] = inv;
        g_topk_w[t * 2 + 1] = w1 * inv;
        atomicAdd(&g_cnt[i0], 1);
        atomicAdd(&g_cnt[i1], 1);
    }
}

__global__ void scan_kernel() {
    if (threadIdx.x == 0) {
        int s = 0;
        for (int e = 0; e < E_NUM; e++) { g_off[e] = s; g_fill[e] = s; s += g_cnt[e]; }
    }
}

__global__ void __launch_bounds__(256) scatter_kernel() {
    const int t = blockIdx.x * 256 + threadIdx.x;
    if (t >= T_TOT) return;
#pragma unroll
    for (int k = 0; k < TOPK; k++) {
        const int e = g_topk_idx[t * 2 + k];
        const float w = g_topk_w[t * 2 + k];
        const int p = atomicAdd(&g_fill[e], 1);
        g_tok[p] = t;
        g_aw[p] = w;
        g_pos[t * 2 + k] = p;
    }
}

// ======================= preprocessing =======================
__global__ void __launch_bounds__(256) split_x_kernel(const float* __restrict__ X) {
    const size_t i = ((size_t)blockIdx.x * 256 + threadIdx.x) * 8;
    const float4 a = *(const float4*)(X + i);
    const float4 b = *(const float4*)(X + i + 4);
    uint32_t h0, l0, h1, l1, h2, l2, h3, l3;
    splitpair(a.x, a.y, h0, l0);
    splitpair(a.z, a.w, h1, l1);
    splitpair(b.x, b.y, h2, l2);
    splitpair(b.z, b.w, h3, l3);
    uint4 H = {h0, h1, h2, h3}, L = {l0, l1, l2, l3};
    *(uint4*)(g_xhi + i) = H;
    *(uint4*)(g_xlo + i) = L;
}

__global__ void __launch_bounds__(256) trans_split_kernel(const float* __restrict__ src,
                                                          bf16* __restrict__ dhi,
                                                          bf16* __restrict__ dlo,
                                                          int R, int C) {
    __shared__ float t[32][33];
    const size_t sb = (size_t)blockIdx.z * R * C;
    const int c0 = blockIdx.x * 32, r0 = blockIdx.y * 32;
    const int tx = threadIdx.x & 31, ty = threadIdx.x >> 5;
#pragma unroll
    for (int j = 0; j < 32; j += 8)
        t[ty + j][tx] = src[sb + (size_t)(r0 + ty + j) * C + c0 + tx];
    __syncthreads();
#pragma unroll
    for (int j = 0; j < 32; j += 8) {
        const float v = t[tx][ty + j];
        bf16 h = __float2bfloat16(v);
        bf16 l = __float2bfloat16(v - __bfloat162float(h));
        const size_t o = sb + (size_t)(c0 + ty + j) * R + r0 + tx;
        dhi[o] = h;
        dlo[o] = l;
    }
}

// ======================= gate+up GEMM (mma.sync bf16, 3-term split) =======================
// CTA tile: M=128, N=64 (of I) for BOTH gate and up. K chunk 64. smem stage 64KB, double buffered.
#define GU_AH  0u
#define GU_AL  16384u
#define GU_BGH 32768u
#define GU_BGL 40960u
#define GU_BUH 49152u
#define GU_BUL 57344u
#define STAGE  65536u
#define GEMM_SMEM (2 * 65536)

template <bool ROUTED>
__global__ void __launch_bounds__(256) gu_mma_kernel(const bf16* __restrict__ BgH,
                                                     const bf16* __restrict__ BgL,
                                                     const bf16* __restrict__ BuH,
                                                     const bf16* __restrict__ BuL,
                                                     bf16* __restrict__ oHi,
                                                     bf16* __restrict__ oLo) {
    const int e   = ROUTED ? blockIdx.z : 0;
    const int cnt = ROUTED ? g_cnt[e] : T_TOT;
    const int off = ROUTED ? g_off[e] : 0;
    const int mb  = blockIdx.y * 128;
    if (mb >= cnt) return;
    const int nb  = blockIdx.x * 64;

    extern __shared__ char dsm[];
    __shared__ int stok[128];
    const uint32_t sb = smem_u32(dsm);

    const int tid = threadIdx.x;
    if (tid < 128) {
        int r = mb + tid;
        if (r >= cnt) r = cnt - 1;
        stok[tid] = ROUTED ? g_tok[off + r] : r;
    }
    __syncthreads();

    // ---- producer mapping ----
    const int cx = tid & 7;           // 16B unit within 128B row
    const int rb = tid >> 3;          // 0..31
    const uint32_t so = (uint32_t)rb * 128u + (uint32_t)(((cx ^ (rb & 7))) * 16);
    const size_t wofs = (size_t)e * I_DIM * H_DIM;

    const bf16 *aHiP[4], *aLoP[4], *bgHp[2], *bgLp[2], *buHp[2], *buLp[2];
#pragma unroll
    for (int j = 0; j < 4; j++) {
        const size_t arow = (size_t)stok[rb + 32 * j] * H_DIM + cx * 8;
        aHiP[j] = g_xhi + arow;
        aLoP[j] = g_xlo + arow;
    }
#pragma unroll
    for (int j = 0; j < 2; j++) {
        const size_t brow = wofs + (size_t)(nb + rb + 32 * j) * H_DIM + cx * 8;
        bgHp[j] = BgH + brow; bgLp[j] = BgL + brow;
        buHp[j] = BuH + brow; buLp[j] = BuL + brow;
    }

    // ---- consumer mapping ----
    const int warp = tid >> 5, lane = tid & 31;
    const int m0 = (warp & 3) * 32;
    const int n0 = (warp >> 2) * 32;
    const int hl = lane >> 4;         // ldmatrix addr: k-half select
    const int l15 = lane & 15;

    uint32_t aRow[2], aXor[2], bRow[2], bXor[2];
#pragma unroll
    for (int mt = 0; mt < 2; mt++) {
        const int r = m0 + mt * 16 + l15;
        aRow[mt] = (uint32_t)r * 128u;
        aXor[mt] = (uint32_t)(r & 7);
    }
#pragma unroll
    for (int p = 0; p < 2; p++) {
        const int r = n0 + p * 16 + l15;
        bRow[p] = (uint32_t)r * 128u;
        bXor[p] = (uint32_t)(r & 7);
    }

    float accg[2][4][4], accu[2][4][4];
#pragma unroll
    for (int mt = 0; mt < 2; mt++)
#pragma unroll
        for (int nt = 0; nt < 4; nt++)
#pragma unroll
            for (int q = 0; q < 4; q++) { accg[mt][nt][q] = 0.0f; accu[mt][nt][q] = 0.0f; }

    const int NCH = H_DIM / KC;   // 16
    // prologue load
    {
        const uint32_t d = sb;
#pragma unroll
        for (int j = 0; j < 4; j++) {
            cp16(d + GU_AH + so + j * 4096u, aHiP[j]);
            cp16(d + GU_AL + so + j * 4096u, aLoP[j]);
        }
#pragma unroll
        for (int j = 0; j < 2; j++) {
            cp16(d + GU_BGH + so + j * 4096u, bgHp[j]);
            cp16(d + GU_BGL + so + j * 4096u, bgLp[j]);
            cp16(d + GU_BUH + so + j * 4096u, buHp[j]);
            cp16(d + GU_BUL + so + j * 4096u, buLp[j]);
        }
        cp_commit();
    }

    for (int c = 0; c < NCH; c++) {
        if (c + 1 < NCH) {
            const uint32_t d = sb + ((c + 1) & 1) * STAGE;
            const int k0 = (c + 1) * KC;
#pragma unroll
            for (int j = 0; j < 4; j++) {
                cp16(d + GU_AH + so + j * 4096u, aHiP[j] + k0);
                cp16(d + GU_AL + so + j * 4096u, aLoP[j] + k0);
            }
#pragma unroll
            for (int j = 0; j < 2; j++) {
                cp16(d + GU_BGH + so + j * 4096u, bgHp[j] + k0);
                cp16(d + GU_BGL + so + j * 4096u, bgLp[j] + k0);
                cp16(d + GU_BUH + so + j * 4096u, buHp[j] + k0);
                cp16(d + GU_BUL + so + j * 4096u, buLp[j] + k0);
            }
            cp_commit();
            cp_wait<1>();
        } else {
            cp_wait<0>();
        }
        __syncthreads();

        const uint32_t st = sb + (c & 1) * STAGE;
#pragma unroll
        for (int kk = 0; kk < 4; kk++) {
            const uint32_t ku = (uint32_t)(2 * kk + hl);
            uint32_t ah[2][4], al[2][4];
#pragma unroll
            for (int mt = 0; mt < 2; mt++) {
                const uint32_t ao = aRow[mt] + ((ku ^ aXor[mt]) << 4);
                ldsm4(ah[mt], st + GU_AH + ao);
                ldsm4(al[mt], st + GU_AL + ao);
            }
            uint32_t bgh[2][4], bgl[2][4], buh[2][4], bul[2][4];
#pragma unroll
            for (int p = 0; p < 2; p++) {
                const uint32_t bo = bRow[p] + ((ku ^ bXor[p]) << 4);
                ldsm4(bgh[p], st + GU_BGH + bo);
                ldsm4(bgl[p], st + GU_BGL + bo);
                ldsm4(buh[p], st + GU_BUH + bo);
                ldsm4(bul[p], st + GU_BUL + bo);
            }
#pragma unroll
            for (int mt = 0; mt < 2; mt++)
#pragma unroll
                for (int p = 0; p < 2; p++)
#pragma unroll
                    for (int q = 0; q < 2; q++) {
                        const int nt = 2 * p + q;
                        mma16816(accg[mt][nt], ah[mt], bgh[p][q], bgh[p][q + 2]);
                        mma16816(accg[mt][nt], ah[mt], bgl[p][q], bgl[p][q + 2]);
                        mma16816(accg[mt][nt], al[mt], bgh[p][q], bgh[p][q + 2]);
                        mma16816(accu[mt][nt], ah[mt], buh[p][q], buh[p][q + 2]);
                        mma16816(accu[mt][nt], ah[mt], bul[p][q], bul[p][q + 2]);
                        mma16816(accu[mt][nt], al[mt], buh[p][q], buh[p][q + 2]);
                    }
        }
        __syncthreads();
    }

    // ---- epilogue: inter = gelu(g)*u, split to bf16 hi/lo ----
    const int colq = (lane & 3) * 2;
#pragma unroll
    for (int mt = 0; mt < 2; mt++) {
#pragma unroll
        for (int half = 0; half < 2; half++) {
            const int gm = mb + m0 + mt * 16 + (lane >> 2) + half * 8;
            if (gm >= cnt) continue;
            const size_t orow = ((size_t)(ROUTED ? off + gm : gm)) * I_DIM;
#pragma unroll
            for (int nt = 0; nt < 4; nt++) {
                const float g0 = accg[mt][nt][half * 2 + 0];
                const float g1 = accg[mt][nt][half * 2 + 1];
                const float u0 = accu[mt][nt][half * 2 + 0];
                const float u1 = accu[mt][nt][half * 2 + 1];
                const float v0 = gelu_exact(g0) * u0;
                const float v1 = gelu_exact(g1) * u1;
                uint32_t h, l;
                splitpair(v0, v1, h, l);
                const size_t oc = orow + nb + n0 + nt * 8 + colq;
                *(uint32_t*)(oHi + oc) = h;
                *(uint32_t*)(oLo + oc) = l;
            }
        }
    }
}

// ======================= down GEMM =======================
// CTA tile: M=128, N=128 (of H). K chunk 64 over I.
#define DN_AH 0u
#define DN_AL 16384u
#define DN_BH 32768u
#define DN_BL 49152u

template <bool ROUTED>
__global__ void __launch_bounds__(256) dn_mma_kernel(const bf16* __restrict__ AHi,
                                                     const bf16* __restrict__ ALo,
                                                     const bf16* __restrict__ BH,
                                                     const bf16* __restrict__ BL,
                                                     float* __restrict__ out) {
    const int e   = ROUTED ? blockIdx.z : 0;
    const int cnt = ROUTED ? g_cnt[e] : T_TOT;
    const int off = ROUTED ? g_off[e] : 0;
    const int mb  = blockIdx.y * 128;
    if (mb >= cnt) return;
    const int nb  = blockIdx.x * 128;

    extern __shared__ char dsm[];
    const uint32_t sb = smem_u32(dsm);
    const int tid = threadIdx.x;

    const int cx = tid & 7;
    const int rb = tid >> 3;
    const uint32_t so = (uint32_t)rb * 128u + (uint32_t)(((cx ^ (rb & 7))) * 16);
    const size_t wofs = (size_t)e * H_DIM * I_DIM;

    const bf16 *aHiP[4], *aLoP[4], *bHp[4], *bLp[4];
#pragma unroll
    for (int j = 0; j < 4; j++) {
        int lr = mb + rb + 32 * j;
        if (lr >= cnt) lr = cnt - 1;
        const size_t arow = (size_t)(off + lr) * I_DIM + cx * 8;
        aHiP[j] = AHi + arow;
        aLoP[j] = ALo + arow;
        const size_t brow = wofs + (size_t)(nb + rb + 32 * j) * I_DIM + cx * 8;
        bHp[j] = BH + brow;
        bLp[j] = BL + brow;
    }

    const int warp = tid >> 5, lane = tid & 31;
    const int m0 = (warp & 3) * 32;
    const int n0 = (warp >> 2) * 64;
    const int hl = lane >> 4;
    const int l15 = lane & 15;

    uint32_t aRow[2], aXor[2], bRow[4], bXor[4];
#pragma unroll
    for (int mt = 0; mt < 2; mt++) {
        const int r = m0 + mt * 16 + l15;
        aRow[mt] = (uint32_t)r * 128u;
        aXor[mt] = (uint32_t)(r & 7);
    }
#pragma unroll
    for (int p = 0; p < 4; p++) {
        const int r = n0 + p * 16 + l15;
        bRow[p] = (uint32_t)r * 128u;
        bXor[p] = (uint32_t)(r & 7);
    }

    float acc[2][8][4];
#pragma unroll
    for (int mt = 0; mt < 2; mt++)
#pragma unroll
        for (int nt = 0; nt < 8; nt++)
#pragma unroll
            for (int q = 0; q < 4; q++) acc[mt][nt][q] = 0.0f;

    const int NCH = I_DIM / KC;   // 8
    {
        const uint32_t d = sb;
#pragma unroll
        for (int j = 0; j < 4; j++) {
            cp16(d + DN_AH + so + j * 4096u, aHiP[j]);
            cp16(d + DN_AL + so + j * 4096u, aLoP[j]);
            cp16(d + DN_BH + so + j * 4096u, bHp[j]);
            cp16(d + DN_BL + so + j * 4096u, bLp[j]);
        }
        cp_commit();
    }

    for (int c = 0; c < NCH; c++) {
        if (c + 1 < NCH) {
            const uint32_t d = sb + ((c + 1) & 1) * STAGE;
            const int k0 = (c + 1) * KC;
#pragma unroll
            for (int j = 0; j < 4; j++) {
                cp16(d + DN_AH + so + j * 4096u, aHiP[j] + k0);
                cp16(d + DN_AL + so + j * 4096u, aLoP[j] + k0);
                cp16(d + DN_BH + so + j * 4096u, bHp[j] + k0);
                cp16(d + DN_BL + so + j * 4096u, bLp[j] + k0);
            }
            cp_commit();
            cp_wait<1>();
        } else {
            cp_wait<0>();
        }
        __syncthreads();

        const uint32_t st = sb + (c & 1) * STAGE;
#pragma unroll
        for (int kk = 0; kk < 4; kk++) {
            const uint32_t ku = (uint32_t)(2 * kk + hl);
            uint32_t ah[2][4], al[2][4];
#pragma unroll
            for (int mt = 0; mt < 2; mt++) {
                const uint32_t ao = aRow[mt] + ((ku ^ aXor[mt]) << 4);
                ldsm4(ah[mt], st + DN_AH + ao);
                ldsm4(al[mt], st + DN_AL + ao);
            }
            uint32_t bh[4][4], bl[4][4];
#pragma unroll
            for (int p = 0; p < 4; p++) {
                const uint32_t bo = bRow[p] + ((ku ^ bXor[p]) << 4);
                ldsm4(bh[p], st + DN_BH + bo);
                ldsm4(bl[p], st + DN_BL + bo);
            }
#pragma unroll
            for (int mt = 0; mt < 2; mt++)
#pragma unroll
                for (int p = 0; p < 4; p++)
#pragma unroll
                    for (int q = 0; q < 2; q++) {
                        const int nt = 2 * p + q;
                        mma16816(acc[mt][nt], ah[mt], bh[p][q], bh[p][q + 2]);
                        mma16816(acc[mt][nt], ah[mt], bl[p][q], bl[p][q + 2]);
                        mma16816(acc[mt][nt], al[mt], bh[p][q], bh[p][q + 2]);
                    }
        }
        __syncthreads();
    }

    // ---- epilogue ----
    const int colq = (lane & 3) * 2;
#pragma unroll
    for (int mt = 0; mt < 2; mt++) {
#pragma unroll
        for (int half = 0; half < 2; half++) {
            const int gm = mb + m0 + mt * 16 + (lane >> 2) + half * 8;
            if (gm >= cnt) continue;
            if (ROUTED) {
                const float w = g_aw[off + gm];
                float* op = out + (size_t)(off + gm) * H_DIM + nb + n0 + colq;   // g_dtmp row
#pragma unroll
                for (int nt = 0; nt < 8; nt++) {
                    float2 v = {w * acc[mt][nt][half * 2 + 0], w * acc[mt][nt][half * 2 + 1]};
                    *(float2*)(op + nt * 8) = v;
                }
            } else {
                float* op = out + (size_t)gm * H_DIM + nb + n0 + colq;
#pragma unroll
                for (int nt = 0; nt < 8; nt++) {
                    float2 v = {acc[mt][nt][half * 2 + 0], acc[mt][nt][half * 2 + 1]};
                    *(float2*)(op + nt * 8) = v;
                }
            }
        }
    }
}

// ======================= combine: out[t] += dtmp[p0] + dtmp[p1] =======================
__global__ void __launch_bounds__(256) combine_kernel(float* __restrict__ out) {
    const int t = blockIdx.x;
    const int p0 = g_pos[t * 2 + 0];
    const int p1 = g_pos[t * 2 + 1];
    const int c = threadIdx.x * 4;
    const float4 a = *(const float4*)(g_dtmp + (size_t)p0 * H_DIM + c);
    const float4 b = *(const float4*)(g_dtmp + (size_t)p1 * H_DIM + c);
    float4 o = *(const float4*)(out + (size_t)t * H_DIM + c);
    o.x += a.x + b.x; o.y += a.y + b.y; o.z += a.z + b.z; o.w += a.w + b.w;
    *(float4*)(out + (size_t)t * H_DIM + c) = o;
}

// ======================= launch =======================
extern "C" void kernel_launch(void* const* d_in, const int* in_sizes, int n_in,
                              void* d_out, int out_size) {
    const float* X   = (const float*)d_in[0];
    const float* GW  = (const float*)d_in[1];
    const float* Wg  = (const float*)d_in[2];
    const float* Wu  = (const float*)d_in[3];
    const float* Wd  = (const float*)d_in[4];
    const float* sWg = (const float*)d_in[5];
    const float* sWu = (const float*)d_in[6];
    const float* sWd = (const float*)d_in[7];
    float* out = (float*)d_out;

    cudaFuncSetAttribute(gu_mma_kernel<true>,  cudaFuncAttributeMaxDynamicSharedMemorySize, GEMM_SMEM);
    cudaFuncSetAttribute(gu_mma_kernel<false>, cudaFuncAttributeMaxDynamicSharedMemorySize, GEMM_SMEM);
    cudaFuncSetAttribute(dn_mma_kernel<true>,  cudaFuncAttributeMaxDynamicSharedMemorySize, GEMM_SMEM);
    cudaFuncSetAttribute(dn_mma_kernel<false>, cudaFuncAttributeMaxDynamicSharedMemorySize, GEMM_SMEM);

    bf16 *xhi, *xlo, *wgTh, *wgTl, *wuTh, *wuTl, *wdTh, *wdTl;
    bf16 *sgTh, *sgTl, *suTh, *suTl, *sdTh, *sdTl, *ihi, *ilo, *sihi, *silo;
    float* dtmp;
    cudaGetSymbolAddress((void**)&xhi, g_xhi);   cudaGetSymbolAddress((void**)&xlo, g_xlo);
    cudaGetSymbolAddress((void**)&wgTh, g_wgT_hi); cudaGetSymbolAddress((void**)&wgTl, g_wgT_lo);
    cudaGetSymbolAddress((void**)&wuTh, g_wuT_hi); cudaGetSymbolAddress((void**)&wuTl, g_wuT_lo);
    cudaGetSymbolAddress((void**)&wdTh, g_wdT_hi); cudaGetSymbolAddress((void**)&wdTl, g_wdT_lo);
    cudaGetSymbolAddress((void**)&sgTh, g_swgT_hi); cudaGetSymbolAddress((void**)&sgTl, g_swgT_lo);
    cudaGetSymbolAddress((void**)&suTh, g_swuT_hi); cudaGetSymbolAddress((void**)&suTl, g_swuT_lo);
    cudaGetSymbolAddress((void**)&sdTh, g_swdT_hi); cudaGetSymbolAddress((void**)&sdTl, g_swdT_lo);
    cudaGetSymbolAddress((void**)&ihi, g_ihi);   cudaGetSymbolAddress((void**)&ilo, g_ilo);
    cudaGetSymbolAddress((void**)&sihi, g_sihi); cudaGetSymbolAddress((void**)&silo, g_silo);
    cudaGetSymbolAddress((void**)&dtmp, g_dtmp);

    // routing
    init_kernel<<<1, 32>>>();
    router_kernel<<<T_TOT / 8, 256>>>(X, GW);
    scan_kernel<<<1, 32>>>();
    scatter_kernel<<<T_TOT / 256, 256>>>();

    // preprocessing
    split_x_kernel<<<(T_TOT * H_DIM) / (256 * 8), 256>>>(X);
    trans_split_kernel<<<dim3(I_DIM / 32, H_DIM / 32, E_NUM), 256>>>(Wg, wgTh, wgTl, H_DIM, I_DIM);
    trans_split_kernel<<<dim3(I_DIM / 32, H_DIM / 32, E_NUM), 256>>>(Wu, wuTh, wuTl, H_DIM, I_DIM);
    trans_split_kernel<<<dim3(H_DIM / 32, I_DIM / 32, E_NUM), 256>>>(Wd, wdTh, wdTl, I_DIM, H_DIM);
    trans_split_kernel<<<dim3(I_DIM / 32, H_DIM / 32, 1), 256>>>(sWg, sgTh, sgTl, H_DIM, I_DIM);
    trans_split_kernel<<<dim3(I_DIM / 32, H_DIM / 32, 1), 256>>>(sWu, suTh, suTl, H_DIM, I_DIM);
    trans_split_kernel<<<dim3(H_DIM / 32, I_DIM / 32, 1), 256>>>(sWd, sdTh, sdTl, I_DIM, H_DIM);

    // shared expert: writes out directly
    gu_mma_kernel<false><<<dim3(I_DIM / 64, T_TOT / 128, 1), 256, GEMM_SMEM>>>(
        sgTh, sgTl, suTh, suTl, sihi, silo);
    dn_mma_kernel<false><<<dim3(H_DIM / 128, T_TOT / 128, 1), 256, GEMM_SMEM>>>(
        sihi, silo, sdTh, sdTl, out);

    // routed experts: down writes g_dtmp (per-assignment), then combine
    gu_mma_kernel<true><<<dim3(I_DIM / 64, T_TOT / 128, E_NUM), 256, GEMM_SMEM>>>(
        wgTh, wgTl, wuTh, wuTl, ihi, ilo);
    dn_mma_kernel<true><<<dim3(H_DIM / 128, T_TOT / 128, E_NUM), 256, GEMM_SMEM>>>(
        ihi, ilo, wdTh, wdTl, dtmp);
    combine_kernel<<<T_TOT, 256>>>(out);
}

// round 4
// speedup vs baseline: 4.1000x; 1.5727x over previous
#include <cuda_runtime.h>
#include <cuda_fp16.h>
#include <math.h>
#include <stdint.h>

#define T_TOT   16384
#define H_DIM   1024
#define I_DIM   512
#define E_NUM   8
#define TOPK    2
#define NASSIGN (T_TOT * TOPK)
#define KC      64

typedef __half hf;

// ======================= scratch =======================
__device__ int   g_topk_idx[NASSIGN];
__device__ float g_topk_w[NASSIGN];
__device__ int   g_cnt[E_NUM];
__device__ int   g_off[E_NUM];
__device__ int   g_fill[E_NUM];
__device__ int   g_tok[NASSIGN];
__device__ float g_aw[NASSIGN];
__device__ int   g_pos[NASSIGN];

__device__ __align__(16) hf g_xhi[(size_t)T_TOT * H_DIM];
__device__ __align__(16) hf g_xlo[(size_t)T_TOT * H_DIM];
// transposed fp16 weights, K-major [N,K]
__device__ __align__(16) hf g_wgT[(size_t)E_NUM * I_DIM * H_DIM];
__device__ __align__(16) hf g_wuT[(size_t)E_NUM * I_DIM * H_DIM];
__device__ __align__(16) hf g_wdT[(size_t)E_NUM * H_DIM * I_DIM];
__device__ __align__(16) hf g_swgT[(size_t)I_DIM * H_DIM];
__device__ __align__(16) hf g_swuT[(size_t)I_DIM * H_DIM];
__device__ __align__(16) hf g_swdT[(size_t)H_DIM * I_DIM];
// intermediates (fp16 hi/lo split, A operand of down GEMM)
__device__ __align__(16) hf g_ihi[(size_t)NASSIGN * I_DIM];
__device__ __align__(16) hf g_ilo[(size_t)NASSIGN * I_DIM];
__device__ __align__(16) hf g_sihi[(size_t)T_TOT * I_DIM];
__device__ __align__(16) hf g_silo[(size_t)T_TOT * I_DIM];
__device__ __align__(16) float g_dtmp[(size_t)NASSIGN * H_DIM];

// ======================= helpers =======================
__device__ __forceinline__ uint32_t smem_u32(const void* p) {
    uint32_t a;
    asm("{ .reg .u64 t; cvta.to.shared.u64 t, %1; cvt.u32.u64 %0, t; }" : "=r"(a) : "l"(p));
    return a;
}
__device__ __forceinline__ void cp16(uint32_t dst, const void* src) {
    asm volatile("cp.async.cg.shared.global [%0], [%1], 16;" :: "r"(dst), "l"(src));
}
__device__ __forceinline__ void cp_commit() { asm volatile("cp.async.commit_group;" ::: "memory"); }
template <int N>
__device__ __forceinline__ void cp_wait() { asm volatile("cp.async.wait_group %0;" :: "n"(N) : "memory"); }

__device__ __forceinline__ void ldsm4(uint32_t* r, uint32_t addr) {
    asm volatile("ldmatrix.sync.aligned.m8n8.x4.shared.b16 {%0,%1,%2,%3}, [%4];"
                 : "=r"(r[0]), "=r"(r[1]), "=r"(r[2]), "=r"(r[3]) : "r"(addr));
}
__device__ __forceinline__ void mma16816(float* d, const uint32_t* a, uint32_t b0, uint32_t b1) {
    asm volatile("mma.sync.aligned.m16n8k16.row.col.f32.f16.f16.f32 "
                 "{%0,%1,%2,%3}, {%4,%5,%6,%7}, {%8,%9}, {%0,%1,%2,%3};"
                 : "+f"(d[0]), "+f"(d[1]), "+f"(d[2]), "+f"(d[3])
                 : "r"(a[0]), "r"(a[1]), "r"(a[2]), "r"(a[3]), "r"(b0), "r"(b1));
}
__device__ __forceinline__ float gelu_exact(float x) {
    return 0.5f * x * (1.0f + erff(x * 0.70710678118654752f));
}
__device__ __forceinline__ void splitpair(float v0, float v1, uint32_t& h, uint32_t& l) {
    __half2 ph = __floats2half2_rn(v0, v1);
    float r0 = v0 - __low2float(ph);
    float r1 = v1 - __high2float(ph);
    __half2 pl = __floats2half2_rn(r0, r1);
    h = *reinterpret_cast<uint32_t*>(&ph);
    l = *reinterpret_cast<uint32_t*>(&pl);
}

// ======================= routing =======================
__global__ void init_kernel() {
    if (threadIdx.x < E_NUM) g_cnt[threadIdx.x] = 0;
}

__global__ void __launch_bounds__(256) router_kernel(const float* __restrict__ X,
                                                     const float* __restrict__ GW) {
    __shared__ float sgw[E_NUM * H_DIM];
    for (int i = threadIdx.x; i < E_NUM * H_DIM; i += 256) sgw[i] = GW[i];
    __syncthreads();
    const int warp = threadIdx.x >> 5, lane = threadIdx.x & 31;
    const int t = blockIdx.x * 8 + warp;
    if (t >= T_TOT) return;
    const float* x = X + (size_t)t * H_DIM;
    float acc[E_NUM];
#pragma unroll
    for (int e = 0; e < E_NUM; e++) acc[e] = 0.0f;
    for (int h = lane; h < H_DIM; h += 32) {
        const float xv = x[h];
#pragma unroll
        for (int e = 0; e < E_NUM; e++) acc[e] = fmaf(xv, sgw[e * H_DIM + h], acc[e]);
    }
#pragma unroll
    for (int e = 0; e < E_NUM; e++)
#pragma unroll
        for (int o = 16; o > 0; o >>= 1) acc[e] += __shfl_down_sync(0xffffffffu, acc[e], o);
    if (lane == 0) {
        float l0 = -1e30f, l1 = -1e30f;
        int i0 = 0, i1 = 0;
#pragma unroll
        for (int e = 0; e < E_NUM; e++) {
            const float v = acc[e];
            if (v > l0)      { l1 = l0; i1 = i0; l0 = v; i0 = e; }
            else if (v > l1) { l1 = v; i1 = e; }
        }
        const float w1 = expf(l1 - l0);
        const float inv = 1.0f / (1.0f + w1);
        g_topk_idx[t * 2 + 0] = i0;
        g_topk_idx[t * 2 + 1] = i1;
        g_topk_w[t * 2 + 0] = inv;
        g_topk_w[t * 2 + 1] = w1 * inv;
        atomicAdd(&g_cnt[i0], 1);
        atomicAdd(&g_cnt[i1], 1);
    }
}

__global__ void scan_kernel() {
    if (threadIdx.x == 0) {
        int s = 0;
        for (int e = 0; e < E_NUM; e++) { g_off[e] = s; g_fill[e] = s; s += g_cnt[e]; }
    }
}

__global__ void __launch_bounds__(256) scatter_kernel() {
    const int t = blockIdx.x * 256 + threadIdx.x;
    if (t >= T_TOT) return;
#pragma unroll
    for (int k = 0; k < TOPK; k++) {
        const int e = g_topk_idx[t * 2 + k];
        const float w = g_topk_w[t * 2 + k];
        const int p = atomicAdd(&g_fill[e], 1);
        g_tok[p] = t;
        g_aw[p] = w;
        g_pos[t * 2 + k] = p;
    }
}

// ======================= preprocessing =======================
__global__ void __launch_bounds__(256) split_x_kernel(const float* __restrict__ X) {
    const size_t i = ((size_t)blockIdx.x * 256 + threadIdx.x) * 8;
    const float4 a = *(const float4*)(X + i);
    const float4 b = *(const float4*)(X + i + 4);
    uint32_t h0, l0, h1, l1, h2, l2, h3, l3;
    splitpair(a.x, a.y, h0, l0);
    splitpair(a.z, a.w, h1, l1);
    splitpair(b.x, b.y, h2, l2);
    splitpair(b.z, b.w, h3, l3);
    uint4 H = {h0, h1, h2, h3}, L = {l0, l1, l2, l3};
    *(uint4*)(g_xhi + i) = H;
    *(uint4*)(g_xlo + i) = L;
}

// transpose + round: src [R,C] fp32 -> dst [C,R] fp16
__global__ void __launch_bounds__(256) trans_round_kernel(const float* __restrict__ src,
                                                          hf* __restrict__ dst,
                                                          int R, int C) {
    __shared__ float t[32][33];
    const size_t sb = (size_t)blockIdx.z * R * C;
    const int c0 = blockIdx.x * 32, r0 = blockIdx.y * 32;
    const int tx = threadIdx.x & 31, ty = threadIdx.x >> 5;
#pragma unroll
    for (int j = 0; j < 32; j += 8)
        t[ty + j][tx] = src[sb + (size_t)(r0 + ty + j) * C + c0 + tx];
    __syncthreads();
#pragma unroll
    for (int j = 0; j < 32; j += 8) {
        dst[sb + (size_t)(c0 + ty + j) * R + r0 + tx] = __float2half_rn(t[tx][ty + j]);
    }
}

// ======================= gate+up GEMM (fp16 mma, A 2-term split, B rounded) ==========
// CTA tile M=128, N=64. K chunk 64. stage = AH(16K) AL(16K) BG(8K) BU(8K) = 48KB x2.
#define GU_AH  0u
#define GU_AL  16384u
#define GU_BG  32768u
#define GU_BU  40960u
#define STAGE  49152u
#define GEMM_SMEM (2 * 49152)

template <bool ROUTED>
__global__ void __launch_bounds__(256) gu_mma_kernel(const hf* __restrict__ Bg,
                                                     const hf* __restrict__ Bu,
                                                     hf* __restrict__ oHi,
                                                     hf* __restrict__ oLo) {
    const int e   = ROUTED ? blockIdx.z : 0;
    const int cnt = ROUTED ? g_cnt[e] : T_TOT;
    const int off = ROUTED ? g_off[e] : 0;
    const int mb  = blockIdx.y * 128;
    if (mb >= cnt) return;
    const int nb  = blockIdx.x * 64;

    extern __shared__ char dsm[];
    __shared__ int stok[128];
    const uint32_t sb = smem_u32(dsm);

    const int tid = threadIdx.x;
    if (tid < 128) {
        int r = mb + tid;
        if (r >= cnt) r = cnt - 1;
        stok[tid] = ROUTED ? g_tok[off + r] : r;
    }
    __syncthreads();

    const int cx = tid & 7;
    const int rb = tid >> 3;
    const uint32_t so = (uint32_t)rb * 128u + (uint32_t)(((cx ^ (rb & 7))) * 16);
    const size_t wofs = (size_t)e * I_DIM * H_DIM;

    const hf *aHiP[4], *aLoP[4], *bgP[2], *buP[2];
#pragma unroll
    for (int j = 0; j < 4; j++) {
        const size_t arow = (size_t)stok[rb + 32 * j] * H_DIM + cx * 8;
        aHiP[j] = g_xhi + arow;
        aLoP[j] = g_xlo + arow;
    }
#pragma unroll
    for (int j = 0; j < 2; j++) {
        const size_t brow = wofs + (size_t)(nb + rb + 32 * j) * H_DIM + cx * 8;
        bgP[j] = Bg + brow;
        buP[j] = Bu + brow;
    }

    const int warp = tid >> 5, lane = tid & 31;
    const int m0 = (warp & 3) * 32;
    const int n0 = (warp >> 2) * 32;
    const int hl = lane >> 4;
    const int l15 = lane & 15;

    uint32_t aRow[2], aXor[2], bRow[2], bXor[2];
#pragma unroll
    for (int mt = 0; mt < 2; mt++) {
        const int r = m0 + mt * 16 + l15;
        aRow[mt] = (uint32_t)r * 128u;
        aXor[mt] = (uint32_t)(r & 7);
    }
#pragma unroll
    for (int p = 0; p < 2; p++) {
        const int r = n0 + p * 16 + l15;
        bRow[p] = (uint32_t)r * 128u;
        bXor[p] = (uint32_t)(r & 7);
    }

    float accg[2][4][4], accu[2][4][4];
#pragma unroll
    for (int mt = 0; mt < 2; mt++)
#pragma unroll
        for (int nt = 0; nt < 4; nt++)
#pragma unroll
            for (int q = 0; q < 4; q++) { accg[mt][nt][q] = 0.0f; accu[mt][nt][q] = 0.0f; }

    const int NCH = H_DIM / KC;   // 16
    {
        const uint32_t d = sb;
#pragma unroll
        for (int j = 0; j < 4; j++) {
            cp16(d + GU_AH + so + j * 4096u, aHiP[j]);
            cp16(d + GU_AL + so + j * 4096u, aLoP[j]);
        }
#pragma unroll
        for (int j = 0; j < 2; j++) {
            cp16(d + GU_BG + so + j * 4096u, bgP[j]);
            cp16(d + GU_BU + so + j * 4096u, buP[j]);
        }
        cp_commit();
    }

    for (int c = 0; c < NCH; c++) {
        if (c + 1 < NCH) {
            const uint32_t d = sb + ((c + 1) & 1) * STAGE;
            const int k0 = (c + 1) * KC;
#pragma unroll
            for (int j = 0; j < 4; j++) {
                cp16(d + GU_AH + so + j * 4096u, aHiP[j] + k0);
                cp16(d + GU_AL + so + j * 4096u, aLoP[j] + k0);
            }
#pragma unroll
            for (int j = 0; j < 2; j++) {
                cp16(d + GU_BG + so + j * 4096u, bgP[j] + k0);
                cp16(d + GU_BU + so + j * 4096u, buP[j] + k0);
            }
            cp_commit();
            cp_wait<1>();
        } else {
            cp_wait<0>();
        }
        __syncthreads();

        const uint32_t st = sb + (c & 1) * STAGE;
#pragma unroll
        for (int kk = 0; kk < 4; kk++) {
            const uint32_t ku = (uint32_t)(2 * kk + hl);
            uint32_t ah[2][4], al[2][4];
#pragma unroll
            for (int mt = 0; mt < 2; mt++) {
                const uint32_t ao = aRow[mt] + ((ku ^ aXor[mt]) << 4);
                ldsm4(ah[mt], st + GU_AH + ao);
                ldsm4(al[mt], st + GU_AL + ao);
            }
            uint32_t bg[2][4], bu[2][4];
#pragma unroll
            for (int p = 0; p < 2; p++) {
                const uint32_t bo = bRow[p] + ((ku ^ bXor[p]) << 4);
                ldsm4(bg[p], st + GU_BG + bo);
                ldsm4(bu[p], st + GU_BU + bo);
            }
#pragma unroll
            for (int mt = 0; mt < 2; mt++)
#pragma unroll
                for (int p = 0; p < 2; p++)
#pragma unroll
                    for (int q = 0; q < 2; q++) {
                        const int nt = 2 * p + q;
                        mma16816(accg[mt][nt], ah[mt], bg[p][q], bg[p][q + 2]);
                        mma16816(accg[mt][nt], al[mt], bg[p][q], bg[p][q + 2]);
                        mma16816(accu[mt][nt], ah[mt], bu[p][q], bu[p][q + 2]);
                        mma16816(accu[mt][nt], al[mt], bu[p][q], bu[p][q + 2]);
                    }
        }
        __syncthreads();
    }

    // epilogue: inter = gelu(g)*u, split fp16 hi/lo
    const int colq = (lane & 3) * 2;
#pragma unroll
    for (int mt = 0; mt < 2; mt++) {
#pragma unroll
        for (int half = 0; half < 2; half++) {
            const int gm = mb + m0 + mt * 16 + (lane >> 2) + half * 8;
            if (gm >= cnt) continue;
            const size_t orow = ((size_t)(ROUTED ? off + gm : gm)) * I_DIM;
#pragma unroll
            for (int nt = 0; nt < 4; nt++) {
                const float g0 = accg[mt][nt][half * 2 + 0];
                const float g1 = accg[mt][nt][half * 2 + 1];
                const float u0 = accu[mt][nt][half * 2 + 0];
                const float u1 = accu[mt][nt][half * 2 + 1];
                const float v0 = gelu_exact(g0) * u0;
                const float v1 = gelu_exact(g1) * u1;
                uint32_t h, l;
                splitpair(v0, v1, h, l);
                const size_t oc = orow + nb + n0 + nt * 8 + colq;
                *(uint32_t*)(oHi + oc) = h;
                *(uint32_t*)(oLo + oc) = l;
            }
        }
    }
}

// ======================= down GEMM =======================
// CTA tile M=128, N=128. K chunk 64. stage = AH(16K) AL(16K) B(16K) = 48KB x2.
#define DN_AH 0u
#define DN_AL 16384u
#define DN_B  32768u

template <bool ROUTED>
__global__ void __launch_bounds__(256) dn_mma_kernel(const hf* __restrict__ AHi,
                                                     const hf* __restrict__ ALo,
                                                     const hf* __restrict__ B,
                                                     float* __restrict__ out) {
    const int e   = ROUTED ? blockIdx.z : 0;
    const int cnt = ROUTED ? g_cnt[e] : T_TOT;
    const int off = ROUTED ? g_off[e] : 0;
    const int mb  = blockIdx.y * 128;
    if (mb >= cnt) return;
    const int nb  = blockIdx.x * 128;

    extern __shared__ char dsm[];
    const uint32_t sb = smem_u32(dsm);
    const int tid = threadIdx.x;

    const int cx = tid & 7;
    const int rb = tid >> 3;
    const uint32_t so = (uint32_t)rb * 128u + (uint32_t)(((cx ^ (rb & 7))) * 16);
    const size_t wofs = (size_t)e * H_DIM * I_DIM;

    const hf *aHiP[4], *aLoP[4], *bP[4];
#pragma unroll
    for (int j = 0; j < 4; j++) {
        int lr = mb + rb + 32 * j;
        if (lr >= cnt) lr = cnt - 1;
        const size_t arow = (size_t)(off + lr) * I_DIM + cx * 8;
        aHiP[j] = AHi + arow;
        aLoP[j] = ALo + arow;
        const size_t brow = wofs + (size_t)(nb + rb + 32 * j) * I_DIM + cx * 8;
        bP[j] = B + brow;
    }

    const int warp = tid >> 5, lane = tid & 31;
    const int m0 = (warp & 3) * 32;
    const int n0 = (warp >> 2) * 64;
    const int hl = lane >> 4;
    const int l15 = lane & 15;

    uint32_t aRow[2], aXor[2], bRow[4], bXor[4];
#pragma unroll
    for (int mt = 0; mt < 2; mt++) {
        const int r = m0 + mt * 16 + l15;
        aRow[mt] = (uint32_t)r * 128u;
        aXor[mt] = (uint32_t)(r & 7);
    }
#pragma unroll
    for (int p = 0; p < 4; p++) {
        const int r = n0 + p * 16 + l15;
        bRow[p] = (uint32_t)r * 128u;
        bXor[p] = (uint32_t)(r & 7);
    }

    float acc[2][8][4];
#pragma unroll
    for (int mt = 0; mt < 2; mt++)
#pragma unroll
        for (int nt = 0; nt < 8; nt++)
#pragma unroll
            for (int q = 0; q < 4; q++) acc[mt][nt][q] = 0.0f;

    const int NCH = I_DIM / KC;   // 8
    {
        const uint32_t d = sb;
#pragma unroll
        for (int j = 0; j < 4; j++) {
            cp16(d + DN_AH + so + j * 4096u, aHiP[j]);
            cp16(d + DN_AL + so + j * 4096u, aLoP[j]);
            cp16(d + DN_B  + so + j * 4096u, bP[j]);
        }
        cp_commit();
    }

    for (int c = 0; c < NCH; c++) {
        if (c + 1 < NCH) {
            const uint32_t d = sb + ((c + 1) & 1) * STAGE;
            const int k0 = (c + 1) * KC;
#pragma unroll
            for (int j = 0; j < 4; j++) {
                cp16(d + DN_AH + so + j * 4096u, aHiP[j] + k0);
                cp16(d + DN_AL + so + j * 4096u, aLoP[j] + k0);
                cp16(d + DN_B  + so + j * 4096u, bP[j] + k0);
            }
            cp_commit();
            cp_wait<1>();
        } else {
            cp_wait<0>();
        }
        __syncthreads();

        const uint32_t st = sb + (c & 1) * STAGE;
#pragma unroll
        for (int kk = 0; kk < 4; kk++) {
            const uint32_t ku = (uint32_t)(2 * kk + hl);
            uint32_t ah[2][4], al[2][4];
#pragma unroll
            for (int mt = 0; mt < 2; mt++) {
                const uint32_t ao = aRow[mt] + ((ku ^ aXor[mt]) << 4);
                ldsm4(ah[mt], st + DN_AH + ao);
                ldsm4(al[mt], st + DN_AL + ao);
            }
            uint32_t bh[4][4];
#pragma unroll
            for (int p = 0; p < 4; p++) {
                const uint32_t bo = bRow[p] + ((ku ^ bXor[p]) << 4);
                ldsm4(bh[p], st + DN_B + bo);
            }
#pragma unroll
            for (int mt = 0; mt < 2; mt++)
#pragma unroll
                for (int p = 0; p < 4; p++)
#pragma unroll
                    for (int q = 0; q < 2; q++) {
                        const int nt = 2 * p + q;
                        mma16816(acc[mt][nt], ah[mt], bh[p][q], bh[p][q + 2]);
                        mma16816(acc[mt][nt], al[mt], bh[p][q], bh[p][q + 2]);
                    }
        }
        __syncthreads();
    }

    const int colq = (lane & 3) * 2;
#pragma unroll
    for (int mt = 0; mt < 2; mt++) {
#pragma unroll
        for (int half = 0; half < 2; half++) {
            const int gm = mb + m0 + mt * 16 + (lane >> 2) + half * 8;
            if (gm >= cnt) continue;
            if (ROUTED) {
                const float w = g_aw[off + gm];
                float* op = out + (size_t)(off + gm) * H_DIM + nb + n0 + colq;  // dtmp row
#pragma unroll
                for (int nt = 0; nt < 8; nt++) {
                    float2 v = {w * acc[mt][nt][half * 2 + 0], w * acc[mt][nt][half * 2 + 1]};
                    *(float2*)(op + nt * 8) = v;
                }
            } else {
                float* op = out + (size_t)gm * H_DIM + nb + n0 + colq;
#pragma unroll
                for (int nt = 0; nt < 8; nt++) {
                    float2 v = {acc[mt][nt][half * 2 + 0], acc[mt][nt][half * 2 + 1]};
                    *(float2*)(op + nt * 8) = v;
                }
            }
        }
    }
}

// ======================= combine =======================
__global__ void __launch_bounds__(256) combine_kernel(float* __restrict__ out) {
    const int t = blockIdx.x;
    const int p0 = g_pos[t * 2 + 0];
    const int p1 = g_pos[t * 2 + 1];
    const int c = threadIdx.x * 4;
    const float4 a = *(const float4*)(g_dtmp + (size_t)p0 * H_DIM + c);
    const float4 b = *(const float4*)(g_dtmp + (size_t)p1 * H_DIM + c);
    float4 o = *(const float4*)(out + (size_t)t * H_DIM + c);
    o.x += a.x + b.x; o.y += a.y + b.y; o.z += a.z + b.z; o.w += a.w + b.w;
    *(float4*)(out + (size_t)t * H_DIM + c) = o;
}

// ======================= launch =======================
extern "C" void kernel_launch(void* const* d_in, const int* in_sizes, int n_in,
                              void* d_out, int out_size) {
    const float* X   = (const float*)d_in[0];
    const float* GW  = (const float*)d_in[1];
    const float* Wg  = (const float*)d_in[2];
    const float* Wu  = (const float*)d_in[3];
    const float* Wd  = (const float*)d_in[4];
    const float* sWg = (const float*)d_in[5];
    const float* sWu = (const float*)d_in[6];
    const float* sWd = (const float*)d_in[7];
    float* out = (float*)d_out;

    cudaFuncSetAttribute(gu_mma_kernel<true>,  cudaFuncAttributeMaxDynamicSharedMemorySize, GEMM_SMEM);
    cudaFuncSetAttribute(gu_mma_kernel<false>, cudaFuncAttributeMaxDynamicSharedMemorySize, GEMM_SMEM);
    cudaFuncSetAttribute(dn_mma_kernel<true>,  cudaFuncAttributeMaxDynamicSharedMemorySize, GEMM_SMEM);
    cudaFuncSetAttribute(dn_mma_kernel<false>, cudaFuncAttributeMaxDynamicSharedMemorySize, GEMM_SMEM);

    hf *wgT, *wuT, *wdT, *sgT, *suT, *sdT, *ihi, *ilo, *sihi, *silo;
    float* dtmp;
    cudaGetSymbolAddress((void**)&wgT, g_wgT);
    cudaGetSymbolAddress((void**)&wuT, g_wuT);
    cudaGetSymbolAddress((void**)&wdT, g_wdT);
    cudaGetSymbolAddress((void**)&sgT, g_swgT);
    cudaGetSymbolAddress((void**)&suT, g_swuT);
    cudaGetSymbolAddress((void**)&sdT, g_swdT);
    cudaGetSymbolAddress((void**)&ihi, g_ihi);   cudaGetSymbolAddress((void**)&ilo, g_ilo);
    cudaGetSymbolAddress((void**)&sihi, g_sihi); cudaGetSymbolAddress((void**)&silo, g_silo);
    cudaGetSymbolAddress((void**)&dtmp, g_dtmp);

    // routing
    init_kernel<<<1, 32>>>();
    router_kernel<<<T_TOT / 8, 256>>>(X, GW);
    scan_kernel<<<1, 32>>>();
    scatter_kernel<<<T_TOT / 256, 256>>>();

    // preprocessing
    split_x_kernel<<<(T_TOT * H_DIM) / (256 * 8), 256>>>(X);
    trans_round_kernel<<<dim3(I_DIM / 32, H_DIM / 32, E_NUM), 256>>>(Wg, wgT, H_DIM, I_DIM);
    trans_round_kernel<<<dim3(I_DIM / 32, H_DIM / 32, E_NUM), 256>>>(Wu, wuT, H_DIM, I_DIM);
    trans_round_kernel<<<dim3(H_DIM / 32, I_DIM / 32, E_NUM), 256>>>(Wd, wdT, I_DIM, H_DIM);
    trans_round_kernel<<<dim3(I_DIM / 32, H_DIM / 32, 1), 256>>>(sWg, sgT, H_DIM, I_DIM);
    trans_round_kernel<<<dim3(I_DIM / 32, H_DIM / 32, 1), 256>>>(sWu, suT, H_DIM, I_DIM);
    trans_round_kernel<<<dim3(H_DIM / 32, I_DIM / 32, 1), 256>>>(sWd, sdT, I_DIM, H_DIM);

    // shared expert
    gu_mma_kernel<false><<<dim3(I_DIM / 64, T_TOT / 128, 1), 256, GEMM_SMEM>>>(
        sgT, suT, sihi, silo);
    dn_mma_kernel<false><<<dim3(H_DIM / 128, T_TOT / 128, 1), 256, GEMM_SMEM>>>(
        sihi, silo, sdT, out);

    // routed experts
    gu_mma_kernel<true><<<dim3(I_DIM / 64, T_TOT / 128, E_NUM), 256, GEMM_SMEM>>>(
        wgT, wuT, ihi, ilo);
    dn_mma_kernel<true><<<dim3(H_DIM / 128, T_TOT / 128, E_NUM), 256, GEMM_SMEM>>>(
        ihi, ilo, wdT, dtmp);
    combine_kernel<<<T_TOT, 256>>>(out);
}